// round 13
// baseline (speedup 1.0000x reference)
#include <cuda_runtime.h>
#include <math.h>

// RNN_472446402977: 4-layer tanh RNN + FC, fp32. B=512 S=256 D_IN=28 H=128 NC=10.
// R13: recur v6 — 2 rows/CTA, grid 256, 2 CTAs/SM. Changes vs v5:
//  * FMA chains split 8x8 (was 4x16): half the dependent-chain latency.
//  * Reduce uses ALL 256 threads (1 output each: scalar loads conflict-free
//    across banks, 7 FADD tree, 1 tanh) — no idle warps, shorter tail.
// W_hh stays in registers as native (i,i+1) u64 pairs. Proj unchanged.

#define BB 512
#define SS 256
#define DIN 28
#define HH 128
#define NC 10

typedef unsigned long long u64;

// Scratch (allocation-free): each [S][B][H] fp32 = 64MB.
__device__ float g_bufA[SS * BB * HH];
__device__ float g_bufB[SS * BB * HH];
__device__ float g_bufC[SS * BB * HH];

// ---- packed f32x2 helpers -------------------------------------------------
#define FMA2(acc, a, b) asm("fma.rn.f32x2 %0, %1, %2, %0;" : "+l"(acc) : "l"(a), "l"(b))
#define ADD2(acc, a)    asm("add.rn.f32x2 %0, %0, %1;"     : "+l"(acc) : "l"(a))

__device__ __forceinline__ u64 pk(float lo, float hi) {
    u64 r; asm("mov.b64 %0, {%1, %2};" : "=l"(r) : "f"(lo), "f"(hi)); return r;
}
__device__ __forceinline__ void upk(u64 v, float& lo, float& hi) {
    asm("mov.b64 {%0, %1}, %2;" : "=f"(lo), "=f"(hi) : "l"(v));
}

// Accurate tanh regardless of fast-math mapping of tanhf (~1e-6 rel).
__device__ __forceinline__ float my_tanh(float x) {
    float ax = fabsf(x);
    float e  = __expf(-2.0f * ax);
    float r  = (1.0f - e) / (1.0f + e);
    return copysignf(r, x);
}

// ---------------------------------------------------------------------------
// Projection GEMM: out[row][n] = A[row][:] . W[n][:] + bias
// 128x128 tile, 256 threads, 8x8 outputs/thread, f32x2 row-pair accumulators.
// ---------------------------------------------------------------------------
template <int K, int KC, bool SWAPPED>
__global__ __launch_bounds__(256, 2)
void proj_kernel(const float* __restrict__ A, const float* __restrict__ W,
                 const float* __restrict__ b1, const float* __restrict__ b2,
                 float* __restrict__ out) {
    extern __shared__ float sm[];
    float* Ws = sm;               // [K][132]   Ws[k][n] = W[n][k]
    float* As = sm + K * 132;     // [KC][132]  As[k][m]
    __shared__ float bs[HH];

    const int tid = threadIdx.x;

    // Stage W transposed with float4 global reads.
    for (int idx = tid; idx < HH * (K / 4); idx += 256) {
        int n  = idx / (K / 4);
        int kq = idx - n * (K / 4);
        float4 v = *(const float4*)&W[n * K + 4 * kq];
        Ws[(4 * kq + 0) * 132 + n] = v.x;
        Ws[(4 * kq + 1) * 132 + n] = v.y;
        Ws[(4 * kq + 2) * 132 + n] = v.z;
        Ws[(4 * kq + 3) * 132 + n] = v.w;
    }
    if (tid < HH) bs[tid] = b1[tid] + b2[tid];

    const int mg = tid & 15, ng = tid >> 4;
    const int c0 = ng * 8;
    const int row0 = blockIdx.x * 128;

    __syncthreads();

    u64 acc[4][8];
#pragma unroll
    for (int c = 0; c < 8; c++) {
        float bv = bs[c0 + c];
        u64 p = pk(bv, bv);
        acc[0][c] = p; acc[1][c] = p; acc[2][c] = p; acc[3][c] = p;
    }

    for (int kc = 0; kc < K; kc += KC) {
        __syncthreads();
        for (int idx = tid; idx < 128 * (KC / 4); idx += 256) {
            int m  = idx / (KC / 4);
            int kq = idx - m * (KC / 4);
            int row = row0 + m;
            const float* src;
            if (SWAPPED) {
                int t = row >> 9, b = row & 511;   // rows are t*B+b, x is [B][S][D]
                src = A + (b * SS + t) * K + kc + 4 * kq;
            } else {
                src = A + (size_t)row * K + kc + 4 * kq;
            }
            float4 v = *(const float4*)src;
            As[(4 * kq + 0) * 132 + m] = v.x;
            As[(4 * kq + 1) * 132 + m] = v.y;
            As[(4 * kq + 2) * 132 + m] = v.z;
            As[(4 * kq + 3) * 132 + m] = v.w;
        }
        __syncthreads();

#pragma unroll 4
        for (int k = 0; k < KC; k++) {
            const float* asr = &As[k * 132 + 4 * mg];
            ulonglong2 aA = *(const ulonglong2*)asr;
            ulonglong2 aB = *(const ulonglong2*)(asr + 64);
            const float* wsr = &Ws[(kc + k) * 132 + c0];
            float4 wf0 = *(const float4*)wsr;
            float4 wf1 = *(const float4*)(wsr + 4);
            u64 ws[8];
            ws[0] = pk(wf0.x, wf0.x); ws[1] = pk(wf0.y, wf0.y);
            ws[2] = pk(wf0.z, wf0.z); ws[3] = pk(wf0.w, wf0.w);
            ws[4] = pk(wf1.x, wf1.x); ws[5] = pk(wf1.y, wf1.y);
            ws[6] = pk(wf1.z, wf1.z); ws[7] = pk(wf1.w, wf1.w);
#pragma unroll
            for (int c = 0; c < 8; c++) {
                FMA2(acc[0][c], aA.x, ws[c]);
                FMA2(acc[1][c], aA.y, ws[c]);
                FMA2(acc[2][c], aB.x, ws[c]);
                FMA2(acc[3][c], aB.y, ws[c]);
            }
        }
    }

#pragma unroll
    for (int rp = 0; rp < 4; rp++) {
        int mloc = (rp < 2) ? (4 * mg + 2 * rp) : (64 + 4 * mg + 2 * (rp - 2));
        float lo[8], hi[8];
#pragma unroll
        for (int c = 0; c < 8; c++) upk(acc[rp][c], lo[c], hi[c]);
        size_t row = row0 + mloc;
        *(float4*)&out[row * HH + c0]           = make_float4(lo[0], lo[1], lo[2], lo[3]);
        *(float4*)&out[row * HH + c0 + 4]       = make_float4(lo[4], lo[5], lo[6], lo[7]);
        *(float4*)&out[(row + 1) * HH + c0]     = make_float4(hi[0], hi[1], hi[2], hi[3]);
        *(float4*)&out[(row + 1) * HH + c0 + 4] = make_float4(hi[4], hi[5], hi[6], hi[7]);
    }
}

// ---------------------------------------------------------------------------
// Recurrence v6: h_t = tanh(xw_t + h_{t-1} @ Whh^T). 256 CTAs x 256 thr,
// 2 batch rows/CTA, 2 CTAs/SM.
// Compute: warp w owns j-chunk [16w,16w+16); lane g owns i-quad [4g,4g+4).
//   Wu[jj][p] = (Whh[4g+2p][j], Whh[4g+2p+1][j]) in regs. 8 chains of 8 FMA2
//   (jj and jj+8 interleaved), merged with 4 ADD2.
// Partials: psum[w][g][slot 2r+p] u64, pitch 6 (16B-aligned STS.128).
// Reduce: ALL 256 threads, 1 output each: r = tid>>7, i = tid&127.
//   8 scalar LDS.32 (bank-conflict-free), 7 FADD tree, + xw, 1 tanh,
//   scalar h write + scalar seq STG (coalesced). 2 barriers/step.
// ---------------------------------------------------------------------------
__global__ __launch_bounds__(256, 2)
void recur3_kernel(const float* __restrict__ xw, const float* __restrict__ Whh,
                   float* __restrict__ seq) {
    extern __shared__ char smc[];
    float*  Wt   = (float*)smc;            // [128][132] staging (preload only)
    float*  hbuf = (float*)smc;            // [2][128][2] (h_r0,h_r1) pairs
    u64*    psum = (u64*)(smc + 2048);     // [8 w][32 g][6] partials

    const int tid = threadIdx.x;
    const int g   = tid & 31;
    const int w   = tid >> 5;

    // --- Stage Whh^T to smem, then native (i,i+1) u64 pairs to registers ----
    for (int idx = tid; idx < HH * (HH / 4); idx += 256) {
        int i  = idx / 32;
        int jq = idx - i * 32;
        float4 v = *(const float4*)&Whh[i * HH + 4 * jq];
        Wt[(4 * jq + 0) * 132 + i] = v.x;
        Wt[(4 * jq + 1) * 132 + i] = v.y;
        Wt[(4 * jq + 2) * 132 + i] = v.z;
        Wt[(4 * jq + 3) * 132 + i] = v.w;
    }
    __syncthreads();

    u64 Wu[16][2];
#pragma unroll
    for (int jj = 0; jj < 16; jj++) {
        float4 v = *(const float4*)&Wt[(16 * w + jj) * 132 + 4 * g];
        Wu[jj][0] = pk(v.x, v.y);
        Wu[jj][1] = pk(v.z, v.w);
    }
    __syncthreads();

    // --- Overlay runtime smem: zero both h buffers --------------------------
    for (int idx = tid; idx < 2 * 128 * 2; idx += 256) hbuf[idx] = 0.0f;
    __syncthreads();

    // --- Reducer identity: 1 output per thread ------------------------------
    const int r  = tid >> 7;           // batch row 0/1
    const int i  = tid & 127;          // output index
    const int b0 = blockIdx.x * 2;

    const size_t BHH = (size_t)BB * HH;
    const float* xq = xw  + (size_t)(b0 + r) * HH + i;
    float*       sq = seq + (size_t)(b0 + r) * HH + i;

    u64* pst = psum + (size_t)w * 192 + (size_t)g * 6;   // my partial slots
    // float-view reduce base: output (r,i) lives at float index
    //   w*384 + (i>>2)*12 + (2*r + ((i>>1)&1))*2 + (i&1)
    const float* prf = (const float*)psum
                     + (size_t)(i >> 2) * 12 + (size_t)(2 * r + ((i >> 1) & 1)) * 2 + (i & 1);

    float xv = *xq;                    // xw at t=0
    int cur = 0;

    for (int t = 0; t < SS; t++) {
        // prefetch next step's xw
        float xn = 0.f;
        if (t + 1 < SS) xn = xq[(size_t)(t + 1) * BHH];

        // 8 chains of 8 FMA2 (split jj 0-7 / 8-15)
        u64 a00 = 0ull, a10 = 0ull, a01 = 0ull, a11 = 0ull;
        u64 b00 = 0ull, b10 = 0ull, b01 = 0ull, b11 = 0ull;
        const float* hr = hbuf + cur * 256;
#pragma unroll
        for (int jj = 0; jj < 8; jj++) {
            float2 hA = *(const float2*)(hr + 2 * (16 * w + jj));
            float2 hB = *(const float2*)(hr + 2 * (16 * w + jj + 8));
            u64 sA0 = pk(hA.x, hA.x), sA1 = pk(hA.y, hA.y);
            u64 sB0 = pk(hB.x, hB.x), sB1 = pk(hB.y, hB.y);
            FMA2(a00, sA0, Wu[jj][0]);
            FMA2(a10, sA0, Wu[jj][1]);
            FMA2(a01, sA1, Wu[jj][0]);
            FMA2(a11, sA1, Wu[jj][1]);
            FMA2(b00, sB0, Wu[jj + 8][0]);
            FMA2(b10, sB0, Wu[jj + 8][1]);
            FMA2(b01, sB1, Wu[jj + 8][0]);
            FMA2(b11, sB1, Wu[jj + 8][1]);
        }
        ADD2(a00, b00); ADD2(a10, b10); ADD2(a01, b01); ADD2(a11, b11);

        // store partials: slots (2r+p): +0:(r0,p0) +1:(r0,p1) +2:(r1,p0) +3:(r1,p1)
        ulonglong2 s;
        s.x = a00; s.y = a10; *(ulonglong2*)(pst + 0) = s;
        s.x = a01; s.y = a11; *(ulonglong2*)(pst + 2) = s;
        __syncthreads();

        // reduce 8 warp partials (scalar, conflict-free) + xw
        float p0 = prf[0 * 384], p1 = prf[1 * 384], p2 = prf[2 * 384], p3 = prf[3 * 384];
        float p4 = prf[4 * 384], p5 = prf[5 * 384], p6 = prf[6 * 384], p7 = prf[7 * 384];
        float v = ((p0 + p1) + (p2 + p3)) + ((p4 + p5) + (p6 + p7)) + xv;
        float th = my_tanh(v);

        // h for next step + sequence output
        hbuf[(cur ^ 1) * 256 + 2 * i + r] = th;
        sq[(size_t)t * BHH] = th;

        xv = xn;
        __syncthreads();
        cur ^= 1;
    }
}

// ---------------------------------------------------------------------------
// FC: out[b][c] = last[b][:] . fc_w[c][:] + fc_b[c]
// ---------------------------------------------------------------------------
__global__ void fc_kernel(const float* __restrict__ last, const float* __restrict__ fw,
                          const float* __restrict__ fb, float* __restrict__ out) {
    int idx = blockIdx.x * blockDim.x + threadIdx.x;
    if (idx >= BB * NC) return;
    int b = idx / NC;
    int c = idx - b * NC;
    const float4* xr = reinterpret_cast<const float4*>(last + b * HH);
    const float4* wr = reinterpret_cast<const float4*>(fw + c * HH);
    float acc = fb[c];
#pragma unroll
    for (int j = 0; j < HH / 4; j++) {
        float4 x = __ldg(xr + j);
        float4 w = __ldg(wr + j);
        acc = fmaf(x.x, w.x, fmaf(x.y, w.y, fmaf(x.z, w.z, fmaf(x.w, w.w, acc))));
    }
    out[idx] = acc;
}

extern "C" void kernel_launch(void* const* d_in, const int* in_sizes, int n_in,
                              void* d_out, int out_size) {
    const float* x     = (const float*)d_in[0];
    const float* w_ih0 = (const float*)d_in[1];
    const float* w_hh0 = (const float*)d_in[2];
    const float* b_ih0 = (const float*)d_in[3];
    const float* b_hh0 = (const float*)d_in[4];
    const float* w_ih  = (const float*)d_in[5];   // [3][H][H]
    const float* w_hh  = (const float*)d_in[6];   // [3][H][H]
    const float* b_ih  = (const float*)d_in[7];   // [3][H]
    const float* b_hh  = (const float*)d_in[8];   // [3][H]
    const float* fc_w  = (const float*)d_in[9];
    const float* fc_b  = (const float*)d_in[10];
    float* out = (float*)d_out;

    float *bufA, *bufB, *bufC;
    cudaGetSymbolAddress((void**)&bufA, g_bufA);
    cudaGetSymbolAddress((void**)&bufB, g_bufB);
    cudaGetSymbolAddress((void**)&bufC, g_bufC);

    const size_t smP128 = (size_t)(128 * 132 + 64 * 132) * 4;   // 101.4 KB (KC=64)
    const size_t smP28  = (size_t)(28 * 132 + 28 * 132) * 4;    // 29.6 KB
    const size_t smR    = (size_t)(128 * 132) * 4;              // 67.6 KB (staging; overlaid)

    cudaFuncSetAttribute(proj_kernel<HH, 64, false>, cudaFuncAttributeMaxDynamicSharedMemorySize, (int)smP128);
    cudaFuncSetAttribute(proj_kernel<DIN, DIN, true>, cudaFuncAttributeMaxDynamicSharedMemorySize, (int)smP28);
    cudaFuncSetAttribute(recur3_kernel, cudaFuncAttributeMaxDynamicSharedMemorySize, (int)smR);

    const int PROJ_BLOCKS = (SS * BB) / 128;   // 1024

    // Layer 0: x -> xw (bufB) -> seq (bufA)
    proj_kernel<DIN, DIN, true><<<PROJ_BLOCKS, 256, smP28>>>(x, w_ih0, b_ih0, b_hh0, bufB);
    recur3_kernel<<<256, 256, smR>>>(bufB, w_hh0, bufA);

    // Layers 1..3: ping-pong A <-> C, xw always in bufB.
    float* seqs[2] = {bufA, bufC};
    for (int l = 0; l < 3; l++) {
        float* prev = seqs[l & 1];
        float* next = seqs[(l & 1) ^ 1];
        proj_kernel<HH, 64, false><<<PROJ_BLOCKS, 256, smP128>>>(
            prev, w_ih + l * HH * HH, b_ih + l * HH, b_hh + l * HH, bufB);
        recur3_kernel<<<256, 256, smR>>>(bufB, w_hh + l * HH * HH, next);
    }

    // Final FC on last timestep of layer-3 output (bufC).
    const float* last = bufC + (size_t)(SS - 1) * BB * HH;
    fc_kernel<<<(BB * NC + 127) / 128, 128>>>(last, fc_w, fc_b, out);
}

// round 14
// speedup vs baseline: 1.5837x; 1.5837x over previous
#include <cuda_runtime.h>
#include <math.h>

// RNN_472446402977: 4-layer tanh RNN + FC, fp32. B=512 S=256 D_IN=28 H=128 NC=10.
// R14: recur = EXACT v5 (R12, known 176.2us/layer; v6 restructure regressed and
// is reverted). Single change this round: proj inner loop gets register
// double-buffering (load k+1 operands during k's FMA block) to hide LDS latency
// at 4 warps/SMSP. Accumulation order unchanged.

#define BB 512
#define SS 256
#define DIN 28
#define HH 128
#define NC 10

typedef unsigned long long u64;

// Scratch (allocation-free): each [S][B][H] fp32 = 64MB.
__device__ float g_bufA[SS * BB * HH];
__device__ float g_bufB[SS * BB * HH];
__device__ float g_bufC[SS * BB * HH];

// ---- packed f32x2 helpers -------------------------------------------------
#define FMA2(acc, a, b) asm("fma.rn.f32x2 %0, %1, %2, %0;" : "+l"(acc) : "l"(a), "l"(b))
#define ADD2(acc, a)    asm("add.rn.f32x2 %0, %0, %1;"     : "+l"(acc) : "l"(a))

__device__ __forceinline__ u64 pk(float lo, float hi) {
    u64 r; asm("mov.b64 %0, {%1, %2};" : "=l"(r) : "f"(lo), "f"(hi)); return r;
}
__device__ __forceinline__ void upk(u64 v, float& lo, float& hi) {
    asm("mov.b64 {%0, %1}, %2;" : "=f"(lo), "=f"(hi) : "l"(v));
}

// Accurate tanh regardless of fast-math mapping of tanhf (~1e-6 rel).
__device__ __forceinline__ float my_tanh(float x) {
    float ax = fabsf(x);
    float e  = __expf(-2.0f * ax);
    float r  = (1.0f - e) / (1.0f + e);
    return copysignf(r, x);
}

// ---------------------------------------------------------------------------
// Projection GEMM: out[row][n] = A[row][:] . W[n][:] + bias
// 128x128 tile, 256 threads, 8x8 outputs/thread, f32x2 row-pair accumulators.
// R14: register double-buffer of (A-pairs, W-vecs) across k.
// ---------------------------------------------------------------------------
template <int K, int KC, bool SWAPPED>
__global__ __launch_bounds__(256, 2)
void proj_kernel(const float* __restrict__ A, const float* __restrict__ W,
                 const float* __restrict__ b1, const float* __restrict__ b2,
                 float* __restrict__ out) {
    extern __shared__ float sm[];
    float* Ws = sm;               // [K][132]   Ws[k][n] = W[n][k]
    float* As = sm + K * 132;     // [KC][132]  As[k][m]
    __shared__ float bs[HH];

    const int tid = threadIdx.x;

    // Stage W transposed with float4 global reads.
    for (int idx = tid; idx < HH * (K / 4); idx += 256) {
        int n  = idx / (K / 4);
        int kq = idx - n * (K / 4);
        float4 v = *(const float4*)&W[n * K + 4 * kq];
        Ws[(4 * kq + 0) * 132 + n] = v.x;
        Ws[(4 * kq + 1) * 132 + n] = v.y;
        Ws[(4 * kq + 2) * 132 + n] = v.z;
        Ws[(4 * kq + 3) * 132 + n] = v.w;
    }
    if (tid < HH) bs[tid] = b1[tid] + b2[tid];

    const int mg = tid & 15, ng = tid >> 4;
    const int c0 = ng * 8;
    const int row0 = blockIdx.x * 128;

    __syncthreads();

    u64 acc[4][8];
#pragma unroll
    for (int c = 0; c < 8; c++) {
        float bv = bs[c0 + c];
        u64 p = pk(bv, bv);
        acc[0][c] = p; acc[1][c] = p; acc[2][c] = p; acc[3][c] = p;
    }

    for (int kc = 0; kc < K; kc += KC) {
        __syncthreads();
        for (int idx = tid; idx < 128 * (KC / 4); idx += 256) {
            int m  = idx / (KC / 4);
            int kq = idx - m * (KC / 4);
            int row = row0 + m;
            const float* src;
            if (SWAPPED) {
                int t = row >> 9, b = row & 511;   // rows are t*B+b, x is [B][S][D]
                src = A + (b * SS + t) * K + kc + 4 * kq;
            } else {
                src = A + (size_t)row * K + kc + 4 * kq;
            }
            float4 v = *(const float4*)src;
            As[(4 * kq + 0) * 132 + m] = v.x;
            As[(4 * kq + 1) * 132 + m] = v.y;
            As[(4 * kq + 2) * 132 + m] = v.z;
            As[(4 * kq + 3) * 132 + m] = v.w;
        }
        __syncthreads();

        // k=0 operand preload
        ulonglong2 aA = *(const ulonglong2*)&As[4 * mg];
        ulonglong2 aB = *(const ulonglong2*)&As[4 * mg + 64];
        float4 wf0 = *(const float4*)&Ws[kc * 132 + c0];
        float4 wf1 = *(const float4*)&Ws[kc * 132 + c0 + 4];

#pragma unroll 8
        for (int k = 0; k < KC; k++) {
            ulonglong2 nA, nB; float4 nw0, nw1;
            if (k + 1 < KC) {
                const float* asr = &As[(k + 1) * 132 + 4 * mg];
                nA  = *(const ulonglong2*)asr;
                nB  = *(const ulonglong2*)(asr + 64);
                const float* wsr = &Ws[(kc + k + 1) * 132 + c0];
                nw0 = *(const float4*)wsr;
                nw1 = *(const float4*)(wsr + 4);
            }
            u64 ws[8];
            ws[0] = pk(wf0.x, wf0.x); ws[1] = pk(wf0.y, wf0.y);
            ws[2] = pk(wf0.z, wf0.z); ws[3] = pk(wf0.w, wf0.w);
            ws[4] = pk(wf1.x, wf1.x); ws[5] = pk(wf1.y, wf1.y);
            ws[6] = pk(wf1.z, wf1.z); ws[7] = pk(wf1.w, wf1.w);
#pragma unroll
            for (int c = 0; c < 8; c++) {
                FMA2(acc[0][c], aA.x, ws[c]);
                FMA2(acc[1][c], aA.y, ws[c]);
                FMA2(acc[2][c], aB.x, ws[c]);
                FMA2(acc[3][c], aB.y, ws[c]);
            }
            if (k + 1 < KC) { aA = nA; aB = nB; wf0 = nw0; wf1 = nw1; }
        }
    }

#pragma unroll
    for (int rp = 0; rp < 4; rp++) {
        int mloc = (rp < 2) ? (4 * mg + 2 * rp) : (64 + 4 * mg + 2 * (rp - 2));
        float lo[8], hi[8];
#pragma unroll
        for (int c = 0; c < 8; c++) upk(acc[rp][c], lo[c], hi[c]);
        size_t row = row0 + mloc;
        *(float4*)&out[row * HH + c0]           = make_float4(lo[0], lo[1], lo[2], lo[3]);
        *(float4*)&out[row * HH + c0 + 4]       = make_float4(lo[4], lo[5], lo[6], lo[7]);
        *(float4*)&out[(row + 1) * HH + c0]     = make_float4(hi[0], hi[1], hi[2], hi[3]);
        *(float4*)&out[(row + 1) * HH + c0 + 4] = make_float4(hi[4], hi[5], hi[6], hi[7]);
    }
}

// ---------------------------------------------------------------------------
// Recurrence v5 (EXACT R12 code): h_t = tanh(xw_t + h_{t-1} @ Whh^T).
// 256 CTAs x 256 thr, 2 batch rows/CTA, 2 CTAs/SM.
// ---------------------------------------------------------------------------
__global__ __launch_bounds__(256, 2)
void recur2_kernel(const float* __restrict__ xw, const float* __restrict__ Whh,
                   float* __restrict__ seq) {
    extern __shared__ char smc[];
    float*  Wt   = (float*)smc;            // [128][132] staging (preload only)
    float*  hbuf = (float*)smc;            // [2][128][2] (h_r0,h_r1) pairs
    u64*    psum = (u64*)(smc + 2048);     // [8 w][32 g][6] partials

    const int tid = threadIdx.x;
    const int g   = tid & 31;
    const int w   = tid >> 5;

    // --- Stage Whh^T to smem, then native (i,i+1) u64 pairs to registers ----
    for (int idx = tid; idx < HH * (HH / 4); idx += 256) {
        int i  = idx / 32;
        int jq = idx - i * 32;
        float4 v = *(const float4*)&Whh[i * HH + 4 * jq];
        Wt[(4 * jq + 0) * 132 + i] = v.x;
        Wt[(4 * jq + 1) * 132 + i] = v.y;
        Wt[(4 * jq + 2) * 132 + i] = v.z;
        Wt[(4 * jq + 3) * 132 + i] = v.w;
    }
    __syncthreads();

    u64 Wu[16][2];
#pragma unroll
    for (int jj = 0; jj < 16; jj++) {
        float4 v = *(const float4*)&Wt[(16 * w + jj) * 132 + 4 * g];
        Wu[jj][0] = pk(v.x, v.y);
        Wu[jj][1] = pk(v.z, v.w);
    }
    __syncthreads();

    // --- Overlay runtime smem: zero both h buffers --------------------------
    for (int idx = tid; idx < 2 * 128 * 2; idx += 256) hbuf[idx] = 0.0f;
    __syncthreads();

    // --- Reducer identity (threads 0..127) ----------------------------------
    const int r  = tid >> 6;           // 0 or 1 (valid for tid<128)
    const int P  = tid & 63;           // i-pair index: i = 2P, 2P+1
    const int b0 = blockIdx.x * 2;
    const bool red = (tid < 128);

    const size_t BHH = (size_t)BB * HH;
    const float* xq = xw  + (size_t)(b0 + r) * HH + 2 * P;
    float*       sq = seq + (size_t)(b0 + r) * HH + 2 * P;

    u64* pst = psum + (size_t)w * 192 + (size_t)g * 6;   // my partial slots
    const u64* prd = psum + (size_t)(P >> 1) * 6 + 2 * r + (P & 1); // + w*192

    float2 xv = make_float2(0.f, 0.f);
    if (red) xv = *(const float2*)xq;      // xw at t=0
    int cur = 0;

    for (int t = 0; t < SS; t++) {
        // prefetch next step's xw
        float2 xn = make_float2(0.f, 0.f);
        if (red && (t + 1 < SS)) xn = *(const float2*)(xq + (size_t)(t + 1) * BHH);

        u64 a00 = 0ull, a10 = 0ull, a01 = 0ull, a11 = 0ull;  // acc[p][r]
        const float* hr = hbuf + cur * 256;
#pragma unroll
        for (int jj = 0; jj < 16; jj++) {
            float2 h2 = *(const float2*)(hr + 2 * (16 * w + jj));  // (h_r0,h_r1)
            u64 s0 = pk(h2.x, h2.x);
            u64 s1 = pk(h2.y, h2.y);
            FMA2(a00, s0, Wu[jj][0]);
            FMA2(a10, s0, Wu[jj][1]);
            FMA2(a01, s1, Wu[jj][0]);
            FMA2(a11, s1, Wu[jj][1]);
        }
        // store partials: slots (2r+p): +0:(r0,p0) +1:(r0,p1) +2:(r1,p0) +3:(r1,p1)
        ulonglong2 s;
        s.x = a00; s.y = a10; *(ulonglong2*)(pst + 0) = s;
        s.x = a01; s.y = a11; *(ulonglong2*)(pst + 2) = s;
        __syncthreads();

        if (red) {
            u64 p0 = prd[0 * 192], p1 = prd[1 * 192], p2 = prd[2 * 192], p3 = prd[3 * 192];
            u64 p4 = prd[4 * 192], p5 = prd[5 * 192], p6 = prd[6 * 192], p7 = prd[7 * 192];
            ADD2(p0, p1); ADD2(p2, p3); ADD2(p4, p5); ADD2(p6, p7);
            ADD2(p0, p2); ADD2(p4, p6);
            ADD2(p0, p4);
            ADD2(p0, pk(xv.x, xv.y));

            float v0, v1; upk(p0, v0, v1);
            float t0 = my_tanh(v0), t1 = my_tanh(v1);

            // h for next step: hbuf[nxt][i].component r
            float* hw = hbuf + (cur ^ 1) * 256;
            hw[4 * P + r]     = t0;     // i = 2P
            hw[4 * P + 2 + r] = t1;     // i = 2P+1
            // sequence output (STG.64)
            *(float2*)(sq + (size_t)t * BHH) = make_float2(t0, t1);
            xv = xn;
        }
        __syncthreads();
        cur ^= 1;
    }
}

// ---------------------------------------------------------------------------
// FC: out[b][c] = last[b][:] . fc_w[c][:] + fc_b[c]
// ---------------------------------------------------------------------------
__global__ void fc_kernel(const float* __restrict__ last, const float* __restrict__ fw,
                          const float* __restrict__ fb, float* __restrict__ out) {
    int idx = blockIdx.x * blockDim.x + threadIdx.x;
    if (idx >= BB * NC) return;
    int b = idx / NC;
    int c = idx - b * NC;
    const float4* xr = reinterpret_cast<const float4*>(last + b * HH);
    const float4* wr = reinterpret_cast<const float4*>(fw + c * HH);
    float acc = fb[c];
#pragma unroll
    for (int j = 0; j < HH / 4; j++) {
        float4 x = __ldg(xr + j);
        float4 w = __ldg(wr + j);
        acc = fmaf(x.x, w.x, fmaf(x.y, w.y, fmaf(x.z, w.z, fmaf(x.w, w.w, acc))));
    }
    out[idx] = acc;
}

extern "C" void kernel_launch(void* const* d_in, const int* in_sizes, int n_in,
                              void* d_out, int out_size) {
    const float* x     = (const float*)d_in[0];
    const float* w_ih0 = (const float*)d_in[1];
    const float* w_hh0 = (const float*)d_in[2];
    const float* b_ih0 = (const float*)d_in[3];
    const float* b_hh0 = (const float*)d_in[4];
    const float* w_ih  = (const float*)d_in[5];   // [3][H][H]
    const float* w_hh  = (const float*)d_in[6];   // [3][H][H]
    const float* b_ih  = (const float*)d_in[7];   // [3][H]
    const float* b_hh  = (const float*)d_in[8];   // [3][H]
    const float* fc_w  = (const float*)d_in[9];
    const float* fc_b  = (const float*)d_in[10];
    float* out = (float*)d_out;

    float *bufA, *bufB, *bufC;
    cudaGetSymbolAddress((void**)&bufA, g_bufA);
    cudaGetSymbolAddress((void**)&bufB, g_bufB);
    cudaGetSymbolAddress((void**)&bufC, g_bufC);

    const size_t smP128 = (size_t)(128 * 132 + 64 * 132) * 4;   // 101.4 KB (KC=64)
    const size_t smP28  = (size_t)(28 * 132 + 28 * 132) * 4;    // 29.6 KB
    const size_t smR    = (size_t)(128 * 132) * 4;              // 67.6 KB (staging; overlaid)

    cudaFuncSetAttribute(proj_kernel<HH, 64, false>, cudaFuncAttributeMaxDynamicSharedMemorySize, (int)smP128);
    cudaFuncSetAttribute(proj_kernel<DIN, DIN, true>, cudaFuncAttributeMaxDynamicSharedMemorySize, (int)smP28);
    cudaFuncSetAttribute(recur2_kernel, cudaFuncAttributeMaxDynamicSharedMemorySize, (int)smR);

    const int PROJ_BLOCKS = (SS * BB) / 128;   // 1024

    // Layer 0: x -> xw (bufB) -> seq (bufA)
    proj_kernel<DIN, DIN, true><<<PROJ_BLOCKS, 256, smP28>>>(x, w_ih0, b_ih0, b_hh0, bufB);
    recur2_kernel<<<256, 256, smR>>>(bufB, w_hh0, bufA);

    // Layers 1..3: ping-pong A <-> C, xw always in bufB.
    float* seqs[2] = {bufA, bufC};
    for (int l = 0; l < 3; l++) {
        float* prev = seqs[l & 1];
        float* next = seqs[(l & 1) ^ 1];
        proj_kernel<HH, 64, false><<<PROJ_BLOCKS, 256, smP128>>>(
            prev, w_ih + l * HH * HH, b_ih + l * HH, b_hh + l * HH, bufB);
        recur2_kernel<<<256, 256, smR>>>(bufB, w_hh + l * HH * HH, next);
    }

    // Final FC on last timestep of layer-3 output (bufC).
    const float* last = bufC + (size_t)(SS - 1) * BB * HH;
    fc_kernel<<<(BB * NC + 127) / 128, 128>>>(last, fc_w, fc_b, out);
}